// round 14
// baseline (speedup 1.0000x reference)
#include <cuda_runtime.h>
#include <cuda_fp16.h>
#include <cstdint>

// CorrVolume1_4 via mma.sync.m16n8k16 f16 banded GEMM.
// corr[b,d,h,w] = sum_c L[b,h,w,c]*R[b,h,w-d,c]; B=8 H=160 W=320 C=128 D=48.
// Block: 64-w tile x 112-u window. Warp = (16-w strip, 32-u half), 16x32x128 GEMM.
// R14: A fragments loaded directly from global (L1-served), no L smem stage.
//      smem = R only (30.5KB, band overlays) -> 5 CTAs/SM via launch_bounds.

#define BB 8
#define HH 160
#define WW 320
#define CC 128
#define DD 48
#define WT 64
#define RT 112
#define LSTR 136                       // smem row stride in halves (128 + 8 pad)
#define SM_R 0
#define SM_BAND 0                      // overlays R region (dead after MMA loop)
#define BSTR 132
#define SMEM_BYTES (RT * LSTR * 2)     // 30464 (band 25344 fits inside)

extern __shared__ char smem[];

__global__ __launch_bounds__(256, 5)
void corrvol_hmma_kernel(const float* __restrict__ L,
                         const float* __restrict__ R,
                         float* __restrict__ out) {
    const int tid  = threadIdx.x;
    const int wid  = tid >> 5, lane = tid & 31;
    const int w0 = blockIdx.x * WT;
    const int h  = blockIdx.y;
    const int b  = blockIdx.z;

    // ---- load + fp16-convert R window: 112 rows (u = w0-48+row), zero u<0 ----
    const float* Rg = R + (size_t)(b * HH + h) * WW * CC;
    #pragma unroll
    for (int i = 0; i < (RT * CC / 4) / 256; i++) {   // 14 iters
        int idx = tid + i * 256;
        int row = idx >> 5;
        int c4  = (idx & 31) * 4;
        int u = w0 - 48 + row;
        float4 v = make_float4(0.f, 0.f, 0.f, 0.f);
        if (u >= 0) v = *(const float4*)(Rg + (size_t)u * CC + c4);
        __half2 h01 = __floats2half2_rn(v.x, v.y);    // x in low half
        __half2 h23 = __floats2half2_rn(v.z, v.w);
        uint2 pk = make_uint2(*(uint32_t*)&h01, *(uint32_t*)&h23);
        *(uint2*)(smem + SM_R + ((size_t)row * LSTR + c4) * 2) = pk;
    }
    __syncthreads();

    // ---- warp GEMM: warp = (a = wid&3: 16-w strip, uh = wid>>2: 32-u half) ----
    const int a  = wid & 3;
    const int uh = wid >> 2;

    // A fragments straight from global. m16n8k16 A map (lane g = lane>>2, c = lane&3):
    //   A0 = (g,   2c), A1 = (g+8, 2c), A2 = (g, 2c+8), A3 = (g+8, 2c+8), +16 per k-step.
    const float* pA = L + ((size_t)(b * HH + h) * WW + w0 + 16 * a + (lane >> 2)) * CC
                        + 2 * (lane & 3);
    const float* pB = pA + 8 * CC;
    // B loads: row (n) = 16a + uh*32 + t*8 + lane/4; k offset = 2*(lane&3)
    const char* b_base = smem + SM_R +
        ((size_t)(16 * a + uh * 32 + (lane >> 2)) * LSTR + (lane & 3) * 2) * 2;

    float acc[4][4];
    #pragma unroll
    for (int t = 0; t < 4; t++)
        #pragma unroll
        for (int r = 0; r < 4; r++) acc[t][r] = 0.f;

    #pragma unroll
    for (int k = 0; k < 8; k++) {                 // K = 8 x 16
        float2 f0 = *(const float2*)(pA + 16 * k);
        float2 f2 = *(const float2*)(pB + 16 * k);
        float2 f1 = *(const float2*)(pA + 16 * k + 8);
        float2 f3 = *(const float2*)(pB + 16 * k + 8);
        __half2 ha0 = __floats2half2_rn(f0.x, f0.y);
        __half2 ha1 = __floats2half2_rn(f2.x, f2.y);
        __half2 ha2 = __floats2half2_rn(f1.x, f1.y);
        __half2 ha3 = __floats2half2_rn(f3.x, f3.y);
        uint32_t A0 = *(uint32_t*)&ha0, A1 = *(uint32_t*)&ha1;
        uint32_t A2 = *(uint32_t*)&ha2, A3 = *(uint32_t*)&ha3;
        #pragma unroll
        for (int t = 0; t < 4; t++) {
            const char* bp = b_base + (size_t)t * 8 * LSTR * 2 + k * 32;
            uint32_t B0 = *(const uint32_t*)bp;
            uint32_t B1 = *(const uint32_t*)(bp + 16);
            asm volatile(
                "mma.sync.aligned.m16n8k16.row.col.f32.f16.f16.f32 "
                "{%0,%1,%2,%3}, {%4,%5,%6,%7}, {%8,%9}, {%0,%1,%2,%3};"
                : "+f"(acc[t][0]), "+f"(acc[t][1]), "+f"(acc[t][2]), "+f"(acc[t][3])
                : "r"(A0), "r"(A1), "r"(A2), "r"(A3), "r"(B0), "r"(B1));
        }
    }

    // All warps must finish reading R before the band overlay is written.
    __syncthreads();

    // ---- scatter into band[d][wl]: d = m_in + 48 - n, m_in = lane/4 (+8), wl = 16a+m_in ----
    #pragma unroll
    for (int t = 0; t < 4; t++) {
        #pragma unroll
        for (int r = 0; r < 4; r++) {
            int m_in = (lane >> 2) + ((r >= 2) ? 8 : 0);
            int n    = uh * 32 + t * 8 + 2 * (lane & 3) + (r & 1);
            int d    = m_in + 48 - n;
            if (d >= 0 && d < DD)
                *(float*)(smem + SM_BAND + ((size_t)d * BSTR + a * 16 + m_in) * 4) = acc[t][r];
        }
    }
    __syncthreads();

    // ---- coalesced writeout: out[b,d,h,w0+wl] = band[d][wl] ----
    #pragma unroll
    for (int i = 0; i < 3; i++) {                 // 48*16 float4 / 256 = 3
        int g  = tid + i * 256;
        int d  = g >> 4;
        int wl = (g & 15) * 4;
        float4 v = *(float4*)(smem + SM_BAND + ((size_t)d * BSTR + wl) * 4);
        *(float4*)(out + (((size_t)(b * DD + d) * HH + h) * WW) + w0 + wl) = v;
    }
}

extern "C" void kernel_launch(void* const* d_in, const int* in_sizes, int n_in,
                              void* d_out, int out_size) {
    const float* L = (const float*)d_in[0];
    const float* R = (const float*)d_in[1];
    float* out = (float*)d_out;

    cudaFuncSetAttribute(corrvol_hmma_kernel,
                         cudaFuncAttributeMaxDynamicSharedMemorySize, SMEM_BYTES);

    dim3 grid(WW / WT, HH, BB);   // (5, 160, 8) = 6400 blocks
    corrvol_hmma_kernel<<<grid, 256, SMEM_BYTES>>>(L, R, out);
}

// round 15
// speedup vs baseline: 1.0233x; 1.0233x over previous
#include <cuda_runtime.h>
#include <cuda_fp16.h>
#include <cstdint>

// CorrVolume1_4 via mma.sync.m16n8k16 f16 banded GEMM.
// corr[b,d,h,w] = sum_c L[b,h,w,c]*R[b,h,w-d,c]; B=8 H=160 W=320 C=128 D=48.
// Block: 64-w tile x 112-u window. Warp = (16-w strip, 32-u half), 16x32x128 GEMM.
// R15: XOR swizzle (16B chunk ^= row&7) replaces row padding -> 45056B smem
//      -> 5 CTAs/SM. L staged via ldmatrix (R13 structure), band overlays operands.

#define BB 8
#define HH 160
#define WW 320
#define CC 128
#define DD 48
#define WT 64
#define RT 112
#define LROW 256                       // bytes per row (128 halves, no padding)
#define SM_L 0
#define SM_R (WT * LROW)               // 16384
#define SM_BAND 0                      // overlays L/R (dead after MMA loop)
#define BSTR 132
#define SMEM_BYTES (SM_R + RT * LROW)  // 45056 (band 25344 fits inside)

__device__ __forceinline__ uint32_t smem_u32(const void* p) {
    uint32_t a;
    asm("{ .reg .u64 t; cvta.to.shared.u64 t, %1; cvt.u32.u64 %0, t; }" : "=r"(a) : "l"(p));
    return a;
}

// swizzled byte offset within a tile: nominal (row, half-col) -> 16B chunk XOR row&7
__device__ __forceinline__ uint32_t swz(int row, int halfcol) {
    uint32_t chunk = (uint32_t)halfcol >> 3;
    return (uint32_t)row * LROW + (((chunk ^ ((uint32_t)row & 7)) << 4) | (((uint32_t)halfcol & 7) * 2));
}

extern __shared__ char smem[];

__global__ __launch_bounds__(256, 5)
void corrvol_hmma_kernel(const float* __restrict__ L,
                         const float* __restrict__ R,
                         float* __restrict__ out) {
    const uint32_t smb = smem_u32(smem);
    const int tid  = threadIdx.x;
    const int wid  = tid >> 5, lane = tid & 31;
    const int w0 = blockIdx.x * WT;
    const int h  = blockIdx.y;
    const int b  = blockIdx.z;

    // ---- load + fp16-convert L tile: 64 rows x 128 (swizzled store) ----
    const float* Lg = L + ((size_t)(b * HH + h) * WW + w0) * CC;
    #pragma unroll
    for (int i = 0; i < (WT * CC / 4) / 256; i++) {   // 8 iters
        int idx = tid + i * 256;
        int row = idx >> 5;
        int c4  = (idx & 31) * 4;
        float4 v = *(const float4*)(Lg + (size_t)row * CC + c4);
        __half2 h01 = __floats2half2_rn(v.x, v.y);    // x in low half
        __half2 h23 = __floats2half2_rn(v.z, v.w);
        uint2 pk = make_uint2(*(uint32_t*)&h01, *(uint32_t*)&h23);
        *(uint2*)(smem + SM_L + swz(row, c4)) = pk;
    }
    // ---- load + convert R window: 112 rows (u = w0-48+row), zero u<0 ----
    const float* Rg = R + (size_t)(b * HH + h) * WW * CC;
    #pragma unroll
    for (int i = 0; i < (RT * CC / 4) / 256; i++) {   // 14 iters
        int idx = tid + i * 256;
        int row = idx >> 5;
        int c4  = (idx & 31) * 4;
        int u = w0 - 48 + row;
        float4 v = make_float4(0.f, 0.f, 0.f, 0.f);
        if (u >= 0) v = *(const float4*)(Rg + (size_t)u * CC + c4);
        __half2 h01 = __floats2half2_rn(v.x, v.y);
        __half2 h23 = __floats2half2_rn(v.z, v.w);
        uint2 pk = make_uint2(*(uint32_t*)&h01, *(uint32_t*)&h23);
        *(uint2*)(smem + SM_R + swz(row, c4)) = pk;
    }
    __syncthreads();

    // ---- warp GEMM: warp = (a = wid&3: 16-w strip, uh = wid>>2: 32-u half) ----
    const int a  = wid & 3;
    const int uh = wid >> 2;

    // A ldmatrix.x4: matrix = lane>>3 -> {rows 0-7/8-15} x {chunk 0 / chunk 1};
    // per k-step nominal chunk advances by 2. Swizzle XOR key = lane&7 (= row&7).
    const int mat = lane >> 3;
    const uint32_t a_key  = (uint32_t)(lane & 7);
    const uint32_t a_base = smb + SM_L +
        (uint32_t)((a * 16) + ((mat & 1) * 8) + (lane & 7)) * LROW;
    const uint32_t a_chunk0 = (uint32_t)(mat >> 1);
    // B loads: row(t) = 16a + uh*32 + t*8 + g (g = lane>>2 = row&7);
    // B0 nominal chunk = 2k, B1 = 2k+1; within-chunk byte = (lane&3)*4.
    const uint32_t g_key = (uint32_t)(lane >> 2);
    const uint32_t b_row_base = smb + SM_R +
        (uint32_t)(16 * a + uh * 32 + (lane >> 2)) * LROW + (uint32_t)(lane & 3) * 4;

    float acc[4][4];
    #pragma unroll
    for (int t = 0; t < 4; t++)
        #pragma unroll
        for (int r = 0; r < 4; r++) acc[t][r] = 0.f;

    #pragma unroll
    for (int k = 0; k < 8; k++) {                 // K = 8 x 16
        uint32_t A0, A1, A2, A3;
        uint32_t a_addr = a_base + (((a_chunk0 + 2u * k) ^ a_key) << 4);
        asm volatile("ldmatrix.sync.aligned.m8n8.x4.shared.b16 {%0,%1,%2,%3}, [%4];"
                     : "=r"(A0), "=r"(A1), "=r"(A2), "=r"(A3)
                     : "r"(a_addr));
        const uint32_t sw0 = ((2u * k)     ^ g_key) << 4;
        const uint32_t sw1 = ((2u * k + 1) ^ g_key) << 4;
        #pragma unroll
        for (int t = 0; t < 4; t++) {
            uint32_t brow = b_row_base + (uint32_t)(t * 8) * LROW;
            uint32_t B0, B1;
            asm volatile("ld.shared.b32 %0, [%1];" : "=r"(B0) : "r"(brow + sw0));
            asm volatile("ld.shared.b32 %0, [%1];" : "=r"(B1) : "r"(brow + sw1));
            asm volatile(
                "mma.sync.aligned.m16n8k16.row.col.f32.f16.f16.f32 "
                "{%0,%1,%2,%3}, {%4,%5,%6,%7}, {%8,%9}, {%0,%1,%2,%3};"
                : "+f"(acc[t][0]), "+f"(acc[t][1]), "+f"(acc[t][2]), "+f"(acc[t][3])
                : "r"(A0), "r"(A1), "r"(A2), "r"(A3), "r"(B0), "r"(B1));
        }
    }

    // All warps must finish reading L/R before the band overlay is written.
    __syncthreads();

    // ---- scatter into band[d][wl]: d = m_in + 48 - n, m_in = lane/4 (+8), wl = 16a+m_in ----
    #pragma unroll
    for (int t = 0; t < 4; t++) {
        #pragma unroll
        for (int r = 0; r < 4; r++) {
            int m_in = (lane >> 2) + ((r >= 2) ? 8 : 0);
            int n    = uh * 32 + t * 8 + 2 * (lane & 3) + (r & 1);
            int d    = m_in + 48 - n;
            if (d >= 0 && d < DD)
                *(float*)(smem + SM_BAND + ((size_t)d * BSTR + a * 16 + m_in) * 4) = acc[t][r];
        }
    }
    __syncthreads();

    // ---- coalesced writeout: out[b,d,h,w0+wl] = band[d][wl] ----
    #pragma unroll
    for (int i = 0; i < 3; i++) {                 // 48*16 float4 / 256 = 3
        int g  = tid + i * 256;
        int d  = g >> 4;
        int wl = (g & 15) * 4;
        float4 v = *(float4*)(smem + SM_BAND + ((size_t)d * BSTR + wl) * 4);
        *(float4*)(out + (((size_t)(b * DD + d) * HH + h) * WW) + w0 + wl) = v;
    }
}

extern "C" void kernel_launch(void* const* d_in, const int* in_sizes, int n_in,
                              void* d_out, int out_size) {
    const float* L = (const float*)d_in[0];
    const float* R = (const float*)d_in[1];
    float* out = (float*)d_out;

    cudaFuncSetAttribute(corrvol_hmma_kernel,
                         cudaFuncAttributeMaxDynamicSharedMemorySize, SMEM_BYTES);

    dim3 grid(WW / WT, HH, BB);   // (5, 160, 8) = 6400 blocks
    corrvol_hmma_kernel<<<grid, 256, SMEM_BYTES>>>(L, R, out);
}

// round 16
// speedup vs baseline: 1.1417x; 1.1156x over previous
#include <cuda_runtime.h>
#include <cuda_fp16.h>
#include <cstdint>

// CorrVolume1_4 via mma.sync.m16n8k16 f16 banded GEMM.
// corr[b,d,h,w] = sum_c L[b,h,w,c]*R[b,h,w-d,c]; B=8 H=160 W=320 C=128 D=48.
// Block: 64-w tile x 112-u window. Warp = (16-w strip, 32-u half), 16x32x128 GEMM.
// R16: exact R13 config (padded smem, 4 CTAs/SM, band overlay) + B operands via
//      ldmatrix.x4 (2 instr/k-step for all 4 n-tiles) to shorten the MMA phase.

#define BB 8
#define HH 160
#define WW 320
#define CC 128
#define DD 48
#define WT 64
#define RT 112
#define LSTR 136                       // smem row stride in halves (128 + 8 pad); 272B = 17*16
#define SM_L 0
#define SM_R (WT * LSTR * 2)           // 17408
#define SM_BAND 0                      // overlays L/R region (dead after MMA loop)
#define BSTR 132
#define SMEM_BYTES (SM_R + RT * LSTR * 2)   // 47872 (band 25344 fits inside)

__device__ __forceinline__ uint32_t smem_u32(const void* p) {
    uint32_t a;
    asm("{ .reg .u64 t; cvta.to.shared.u64 t, %1; cvt.u32.u64 %0, t; }" : "=r"(a) : "l"(p));
    return a;
}

extern __shared__ char smem[];

__global__ __launch_bounds__(256)
void corrvol_hmma_kernel(const float* __restrict__ L,
                         const float* __restrict__ R,
                         float* __restrict__ out) {
    const uint32_t smb = smem_u32(smem);
    const int tid  = threadIdx.x;
    const int wid  = tid >> 5, lane = tid & 31;
    const int w0 = blockIdx.x * WT;
    const int h  = blockIdx.y;
    const int b  = blockIdx.z;

    // ---- load + fp16-convert L tile: 64 rows x 128 ----
    const float* Lg = L + ((size_t)(b * HH + h) * WW + w0) * CC;
    #pragma unroll
    for (int i = 0; i < (WT * CC / 4) / 256; i++) {   // 8 iters
        int idx = tid + i * 256;
        int row = idx >> 5;
        int c4  = (idx & 31) * 4;
        float4 v = *(const float4*)(Lg + (size_t)row * CC + c4);
        __half2 h01 = __floats2half2_rn(v.x, v.y);    // x in low half
        __half2 h23 = __floats2half2_rn(v.z, v.w);
        uint2 pk = make_uint2(*(uint32_t*)&h01, *(uint32_t*)&h23);
        *(uint2*)(smem + SM_L + ((size_t)row * LSTR + c4) * 2) = pk;
    }
    // ---- load + convert R window: 112 rows (u = w0-48+row), zero u<0 ----
    const float* Rg = R + (size_t)(b * HH + h) * WW * CC;
    #pragma unroll
    for (int i = 0; i < (RT * CC / 4) / 256; i++) {   // 14 iters
        int idx = tid + i * 256;
        int row = idx >> 5;
        int c4  = (idx & 31) * 4;
        int u = w0 - 48 + row;
        float4 v = make_float4(0.f, 0.f, 0.f, 0.f);
        if (u >= 0) v = *(const float4*)(Rg + (size_t)u * CC + c4);
        __half2 h01 = __floats2half2_rn(v.x, v.y);
        __half2 h23 = __floats2half2_rn(v.z, v.w);
        uint2 pk = make_uint2(*(uint32_t*)&h01, *(uint32_t*)&h23);
        *(uint2*)(smem + SM_R + ((size_t)row * LSTR + c4) * 2) = pk;
    }
    __syncthreads();

    // ---- warp GEMM: warp = (a = wid&3: 16-w strip, uh = wid>>2: 32-u half) ----
    const int a  = wid & 3;
    const int uh = wid >> 2;

    // A ldmatrix.x4: matrix = lane>>3 -> {rows 0-7/8-15} x {k0/k+8}
    const int mat = lane >> 3;
    const uint32_t a_addr0 = smb + SM_L +
        (uint32_t)(((a * 16) + ((mat & 1) * 8) + (lane & 7)) * LSTR + ((mat >> 1) * 8)) * 2;

    // B ldmatrix.x4 per (k, t-pair p): matrices = (t=2p: k-lo, k-hi), (t=2p+1: k-lo, k-hi).
    //   lane row  = 16a + 32uh + 16p + ((lane>>4)&1)*8 + (lane&7)
    //   lane chunk (16B) = 2k + ((lane>>3)&1)
    const uint32_t b_addr_p0 = smb + SM_R +
        (uint32_t)((16 * a + 32 * uh + ((lane >> 4) & 1) * 8 + (lane & 7)) * LSTR) * 2 +
        (((uint32_t)(lane >> 3) & 1) << 4);
    const uint32_t b_addr_p1 = b_addr_p0 + 16u * LSTR * 2;

    float acc[4][4];
    #pragma unroll
    for (int t = 0; t < 4; t++)
        #pragma unroll
        for (int r = 0; r < 4; r++) acc[t][r] = 0.f;

    #pragma unroll
    for (int k = 0; k < 8; k++) {                 // K = 8 x 16
        uint32_t A0, A1, A2, A3;
        asm volatile("ldmatrix.sync.aligned.m8n8.x4.shared.b16 {%0,%1,%2,%3}, [%4];"
                     : "=r"(A0), "=r"(A1), "=r"(A2), "=r"(A3)
                     : "r"(a_addr0 + (uint32_t)k * 32));
        uint32_t Bv[8];   // [t*2 + {0,1}] = {B0, B1} for t = 0..3
        asm volatile("ldmatrix.sync.aligned.m8n8.x4.shared.b16 {%0,%1,%2,%3}, [%4];"
                     : "=r"(Bv[0]), "=r"(Bv[1]), "=r"(Bv[2]), "=r"(Bv[3])
                     : "r"(b_addr_p0 + (uint32_t)k * 32));
        asm volatile("ldmatrix.sync.aligned.m8n8.x4.shared.b16 {%0,%1,%2,%3}, [%4];"
                     : "=r"(Bv[4]), "=r"(Bv[5]), "=r"(Bv[6]), "=r"(Bv[7])
                     : "r"(b_addr_p1 + (uint32_t)k * 32));
        #pragma unroll
        for (int t = 0; t < 4; t++) {
            asm volatile(
                "mma.sync.aligned.m16n8k16.row.col.f32.f16.f16.f32 "
                "{%0,%1,%2,%3}, {%4,%5,%6,%7}, {%8,%9}, {%0,%1,%2,%3};"
                : "+f"(acc[t][0]), "+f"(acc[t][1]), "+f"(acc[t][2]), "+f"(acc[t][3])
                : "r"(A0), "r"(A1), "r"(A2), "r"(A3), "r"(Bv[2*t]), "r"(Bv[2*t+1]));
        }
    }

    // All warps must finish reading L/R before the band overlay is written.
    __syncthreads();

    // ---- scatter into band[d][wl]: d = m_in + 48 - n, m_in = lane/4 (+8), wl = 16a+m_in ----
    #pragma unroll
    for (int t = 0; t < 4; t++) {
        #pragma unroll
        for (int r = 0; r < 4; r++) {
            int m_in = (lane >> 2) + ((r >= 2) ? 8 : 0);
            int n    = uh * 32 + t * 8 + 2 * (lane & 3) + (r & 1);
            int d    = m_in + 48 - n;
            if (d >= 0 && d < DD)
                *(float*)(smem + SM_BAND + ((size_t)d * BSTR + a * 16 + m_in) * 4) = acc[t][r];
        }
    }
    __syncthreads();

    // ---- coalesced writeout: out[b,d,h,w0+wl] = band[d][wl] ----
    #pragma unroll
    for (int i = 0; i < 3; i++) {                 // 48*16 float4 / 256 = 3
        int g  = tid + i * 256;
        int d  = g >> 4;
        int wl = (g & 15) * 4;
        float4 v = *(float4*)(smem + SM_BAND + ((size_t)d * BSTR + wl) * 4);
        *(float4*)(out + (((size_t)(b * DD + d) * HH + h) * WW) + w0 + wl) = v;
    }
}

extern "C" void kernel_launch(void* const* d_in, const int* in_sizes, int n_in,
                              void* d_out, int out_size) {
    const float* L = (const float*)d_in[0];
    const float* R = (const float*)d_in[1];
    float* out = (float*)d_out;

    cudaFuncSetAttribute(corrvol_hmma_kernel,
                         cudaFuncAttributeMaxDynamicSharedMemorySize, SMEM_BYTES);

    dim3 grid(WW / WT, HH, BB);   // (5, 160, 8) = 6400 blocks
    corrvol_hmma_kernel<<<grid, 256, SMEM_BYTES>>>(L, R, out);
}